// round 15
// baseline (speedup 1.0000x reference)
#include <cuda_runtime.h>
#include <math.h>

#define Bx 8
#define Nx 512
#define Dx 128
#define Hx 64
#define FNx 3
#define NLx 3
#define OUTC 10
#define BN (Bx*Nx)
#define NBCAP 128
#define NB 128          // grid size: all blocks co-resident
#define NT 512          // threads per block (16 warps)

// ---------------- device scratch (static, no allocation) ----------------
__device__ float    g_kap[BN];
__device__ float    g_f[FNx][BN];
__device__ float    g_m1;
__device__ unsigned g_adj[BN*16];
__device__ unsigned short g_nbr[BN*NBCAP];
__device__ int      g_ndeg[BN];
__device__ unsigned g_kmask1[Bx*16];
__device__ unsigned g_kmask2[Bx*16];
__device__ float    g_deg[BN];
__device__ float    g_u1[FNx][BN];
__device__ float    g_gamma[FNx][BN];
__device__ float    g_df[FNx][BN];
__device__ float    g_fdf[FNx][BN];
__device__ float    g_rowloss[BN];
__device__ float    g_loss;
__device__ __align__(16) float g_h[NLx][BN*Hx];
__device__ float    g_part[Bx*16*320];
__device__ unsigned g_barcnt[8];            // monotonic across graph replays

// ---------------- software grid barrier (all NB blocks co-resident) -------
__device__ __forceinline__ void gridbar(int id)
{
    __syncthreads();
    __threadfence();
    if (threadIdx.x == 0) {
        unsigned tk = atomicAdd(&g_barcnt[id], 1u);
        unsigned base = tk - (tk & (NB - 1));
        while ((*(volatile unsigned*)&g_barcnt[id]) - base < NB) { }
        __threadfence();
    }
    __syncthreads();
}

// ---------------- gin sub-phase: CSR agg + 2-layer MLP + column partials --
// Register-tiled GEMMs: thread owns 2 cols x 2 nodes; float4 act (broadcast)
// + float2 weights => ~16 FMA per 10 LDS-crossbar cycles.
template<int DIN>
__device__ void gin_phase(float* sm, const float* __restrict__ hin,
    const unsigned* __restrict__ kmask, float eps1,
    const float* __restrict__ W1, const float* __restrict__ b1,
    const float* __restrict__ W2, const float* __restrict__ b2,
    float* __restrict__ hout, int partCol)
{
    float* sW1  = sm;                    // DIN*64
    float* sW2  = sW1 + DIN*64;          // 64*64
    float* sAgg = sW2 + 64*64;           // 32*DIN  (reused as sRed in epilogue)
    float* sHid = sAgg + 32*DIN;         // 32*64
    unsigned* skm = (unsigned*)(sHid + 2048);
    const int tid = threadIdx.x;
    const int nodeBase = blockIdx.x * 32;
    const int b = nodeBase >> 9;
    const int pp = (nodeBase >> 5) & 15;

    for (int i = tid; i < DIN*64/4; i += NT) ((float4*)sW1)[i] = ((const float4*)W1)[i];
    for (int i = tid; i < 64*64/4; i += NT)  ((float4*)sW2)[i] = ((const float4*)W2)[i];
    if (tid < 16) skm[tid] = kmask ? kmask[b*16 + tid] : 0xffffffffu;
    __syncthreads();

    const int w = tid >> 5, lane = tid & 31;

    // aggregation: 16 warps x 2 nodes, vectorized loads
    for (int nn = 0; nn < 2; nn++) {
        int nl = w*2 + nn;
        int node = nodeBase + nl;
        int loc = node & 511;
        bool rk = (skm[loc >> 5] >> (loc & 31)) & 1u;
        if (DIN == 128) {
            float4 acc = make_float4(0.f, 0.f, 0.f, 0.f);
            if (rk) {
                int deg = g_ndeg[node];
                const unsigned short* L = g_nbr + (size_t)node*NBCAP;
                #pragma unroll 4
                for (int n = 0; n < deg; n++) {
                    int j = L[n];
                    if ((skm[j >> 5] >> (j & 31)) & 1u) {
                        float4 v = ((const float4*)(hin + ((size_t)(b*Nx + j))*DIN))[lane];
                        acc.x += v.x; acc.y += v.y; acc.z += v.z; acc.w += v.w;
                    }
                }
            }
            float4 hv = ((const float4*)(hin + (size_t)node*DIN))[lane];
            float4 o;
            o.x = eps1*hv.x + acc.x; o.y = eps1*hv.y + acc.y;
            o.z = eps1*hv.z + acc.z; o.w = eps1*hv.w + acc.w;
            *(float4*)&sAgg[nl*DIN + lane*4] = o;
        } else {
            float2 acc = make_float2(0.f, 0.f);
            if (rk) {
                int deg = g_ndeg[node];
                const unsigned short* L = g_nbr + (size_t)node*NBCAP;
                #pragma unroll 4
                for (int n = 0; n < deg; n++) {
                    int j = L[n];
                    if ((skm[j >> 5] >> (j & 31)) & 1u) {
                        float2 v = ((const float2*)(hin + ((size_t)(b*Nx + j))*DIN))[lane];
                        acc.x += v.x; acc.y += v.y;
                    }
                }
            }
            float2 hv = ((const float2*)(hin + (size_t)node*DIN))[lane];
            float2 o;
            o.x = eps1*hv.x + acc.x; o.y = eps1*hv.y + acc.y;
            *(float2*)&sAgg[nl*DIN + lane*2] = o;
        }
    }
    __syncthreads();

    const int cp = tid & 31, gp = tid >> 5;   // col-pair 0..31, group 0..15

    {   // hidden layer: 2 cols x 2 nodes per thread, float4 over d
        const float4* A0 = (const float4*)(sAgg + gp*DIN);
        const float4* A1 = (const float4*)(sAgg + (gp+16)*DIN);
        float2 bc = *(const float2*)(b1 + 2*cp);
        float r00 = bc.x, r01 = bc.y, r10 = bc.x, r11 = bc.y;
        #pragma unroll 4
        for (int d4 = 0; d4 < DIN/4; d4++) {
            float4 a0 = A0[d4], a1 = A1[d4];
            const float* wd = sW1 + d4*256 + 2*cp;
            float2 w0 = *(const float2*)(wd);
            float2 w1 = *(const float2*)(wd + 64);
            float2 w2 = *(const float2*)(wd + 128);
            float2 w3 = *(const float2*)(wd + 192);
            r00 += a0.x*w0.x + a0.y*w1.x + a0.z*w2.x + a0.w*w3.x;
            r01 += a0.x*w0.y + a0.y*w1.y + a0.z*w2.y + a0.w*w3.y;
            r10 += a1.x*w0.x + a1.y*w1.x + a1.z*w2.x + a1.w*w3.x;
            r11 += a1.x*w0.y + a1.y*w1.y + a1.z*w2.y + a1.w*w3.y;
        }
        *(float2*)(sHid + gp*64 + 2*cp)      = make_float2(fmaxf(r00,0.f), fmaxf(r01,0.f));
        *(float2*)(sHid + (gp+16)*64 + 2*cp) = make_float2(fmaxf(r10,0.f), fmaxf(r11,0.f));
    }
    __syncthreads();

    {   // output layer + fused column partials
        const float4* H0 = (const float4*)(sHid + gp*64);
        const float4* H1 = (const float4*)(sHid + (gp+16)*64);
        float2 bc = *(const float2*)(b2 + 2*cp);
        float r00 = bc.x, r01 = bc.y, r10 = bc.x, r11 = bc.y;
        #pragma unroll 4
        for (int d4 = 0; d4 < 16; d4++) {
            float4 a0 = H0[d4], a1 = H1[d4];
            const float* wd = sW2 + d4*256 + 2*cp;
            float2 w0 = *(const float2*)(wd);
            float2 w1 = *(const float2*)(wd + 64);
            float2 w2 = *(const float2*)(wd + 128);
            float2 w3 = *(const float2*)(wd + 192);
            r00 += a0.x*w0.x + a0.y*w1.x + a0.z*w2.x + a0.w*w3.x;
            r01 += a0.x*w0.y + a0.y*w1.y + a0.z*w2.y + a0.w*w3.y;
            r10 += a1.x*w0.x + a1.y*w1.x + a1.z*w2.x + a1.w*w3.x;
            r11 += a1.x*w0.y + a1.y*w1.y + a1.z*w2.y + a1.w*w3.y;
        }
        float p0x = fmaxf(r00,0.f), p0y = fmaxf(r01,0.f);
        float p1x = fmaxf(r10,0.f), p1y = fmaxf(r11,0.f);
        if (hout) {
            *(float2*)(hout + ((size_t)(nodeBase + gp))*64 + 2*cp)    = make_float2(p0x, p0y);
            *(float2*)(hout + ((size_t)(nodeBase + gp+16))*64 + 2*cp) = make_float2(p1x, p1y);
        }
        __syncthreads();   // sHid reads done before sAgg reuse is safe anyway; order partials
        *(float2*)(sAgg + gp*64 + 2*cp) = make_float2(p0x + p1x, p0y + p1y);
    }
    __syncthreads();
    if (tid < 64) {
        float s = 0.f;
        #pragma unroll
        for (int g = 0; g < 16; g++) s += sAgg[g*64 + tid];
        g_part[(b*16 + pp)*320 + partCol + tid] = s;
    }
    __syncthreads();
}

// ---------------- the megakernel ------------------------------------------
__global__ __launch_bounds__(NT, 1)
void mega_kernel(const float* __restrict__ X, const float* __restrict__ A,
    const int* __restrict__ p_ptr,
    const float* __restrict__ cW1, const float* __restrict__ cb1,
    const float* __restrict__ cW2, const float* __restrict__ cb2,
    const float* __restrict__ wmW1, const float* __restrict__ wmb1,
    const float* __restrict__ wmW2, const float* __restrict__ wmb2,
    const float* __restrict__ wmW3, const float* __restrict__ wmb3,
    const float* __restrict__ fW1, const float* __restrict__ fb1,
    const float* __restrict__ fW2, const float* __restrict__ fb2,
    const float* __restrict__ eps,
    const float* __restrict__ g0W1, const float* __restrict__ g0b1,
    const float* __restrict__ g0W2, const float* __restrict__ g0b2,
    const float* __restrict__ g1W1, const float* __restrict__ g1b1,
    const float* __restrict__ g1W2, const float* __restrict__ g1b2,
    const float* __restrict__ g2W1, const float* __restrict__ g2b1,
    const float* __restrict__ g2W2, const float* __restrict__ g2b2,
    const float* __restrict__ outW, const float* __restrict__ outb,
    float* __restrict__ dout, int out_size)
{
    extern __shared__ float sm[];
    __shared__ int wcnt[16];
    const int tid = threadIdx.x, bid = blockIdx.x;
    const int w = tid >> 5, lane = tid & 31;
    const unsigned full = 0xffffffffu;

    // ================= PHASE 1a: adjacency compress + CSR (vectorized) ====
    {
        int warpG = bid*16 + w;              // 0..2047
        for (int k = 0; k < 2; k++) {
            int r = warpG*2 + k;
            const float4* Ar4 = (const float4*)(A + (size_t)r * Nx);
            unsigned wreg[4];
            #pragma unroll
            for (int g = 0; g < 4; g++) {
                float4 v = Ar4[g*32 + lane];
                unsigned nib = (unsigned)(v.x != 0.f)
                             | ((unsigned)(v.y != 0.f) << 1)
                             | ((unsigned)(v.z != 0.f) << 2)
                             | ((unsigned)(v.w != 0.f) << 3);
                unsigned wd = nib << (4*(lane & 7));
                wd |= __shfl_xor_sync(full, wd, 1);
                wd |= __shfl_xor_sync(full, wd, 2);
                wd |= __shfl_xor_sync(full, wd, 4);
                wreg[g] = wd;                // holds word index g*4 + (lane>>3)
            }
            unsigned srcl = (lane & 3) * 8;
            unsigned q0 = __shfl_sync(full, wreg[0], srcl);
            unsigned q1 = __shfl_sync(full, wreg[1], srcl);
            unsigned q2 = __shfl_sync(full, wreg[2], srcl);
            unsigned q3 = __shfl_sync(full, wreg[3], srcl);
            int g2 = lane >> 2;
            unsigned myword = (g2 == 0) ? q0 : (g2 == 1) ? q1 : (g2 == 2) ? q2 : q3;
            if (lane < 16) g_adj[(size_t)r*16 + lane] = myword;
            unsigned wv = (lane < 16) ? myword : 0u;
            int cnt = __popc(wv);
            int ex = cnt;
            #pragma unroll
            for (int o = 1; o < 32; o <<= 1) {
                int nv = __shfl_up_sync(full, ex, o);
                if (lane >= o) ex += nv;
            }
            int total = __shfl_sync(full, ex, 15);
            ex -= cnt;
            if (lane < 16) {
                int pos = ex;
                unsigned bits = wv;
                while (bits) {
                    int j = __ffs(bits) - 1; bits &= bits - 1;
                    if (pos < NBCAP)
                        g_nbr[(size_t)r*NBCAP + pos] = (unsigned short)(lane*32 + j);
                    pos++;
                }
            }
            if (lane == 0) g_ndeg[r] = (total < NBCAP) ? total : NBCAP;
        }
    }

    // ================= PHASE 1b: node MLPs + X column partials ============
    {
        float* sX    = sm;                  // 32*128 = 4096
        float* sW1s  = sm + 4096;           // 128*64 = 8192
        float* sHid  = sm + 4096 + 8192;    // 32*64  = 2048
        float* sW2v  = sHid + 2048;         // 64
        float* sPartX= sm + 14400;          // 512
        int nodeBase = bid * 32;
        int b = bid >> 4, pp = bid & 15;
        __syncthreads();
        for (int i = tid; i < 32*Dx/4; i += NT)
            ((float4*)sX)[i] = ((const float4*)(X + (size_t)nodeBase*Dx))[i];
        __syncthreads();

        // X column partials for readout (cols 0..127)
        {
            int qtr = tid >> 7, col = tid & 127;
            float s = 0.f;
            #pragma unroll
            for (int n = 0; n < 8; n++) s += sX[(qtr*8 + n)*Dx + col];
            sPartX[qtr*128 + col] = s;
        }
        __syncthreads();
        if (tid < 128) {
            float s = sPartX[tid] + sPartX[128+tid] + sPartX[256+tid] + sPartX[384+tid];
            g_part[(b*16 + pp)*320 + tid] = s;
        }

        const int cp = tid & 31, gp = tid >> 5;
        for (int m = 0; m < 4; m++) {
            const float* W1 = (m == 0) ? cW1 : fW1 + (size_t)(m-1)*Dx*Hx;
            const float* B1 = (m == 0) ? cb1 : fb1 + (m-1)*Hx;
            const float* W2 = (m == 0) ? cW2 : fW2 + (m-1)*Hx;
            float B2 = (m == 0) ? cb2[0] : fb2[m-1];
            __syncthreads();
            for (int i = tid; i < Dx*Hx/4; i += NT)
                ((float4*)sW1s)[i] = ((const float4*)W1)[i];
            if (tid < 64) sW2v[tid] = W2[tid];
            __syncthreads();
            {   // hidden: 2 cols x 2 nodes per thread, float4 over d
                const float4* A0 = (const float4*)(sX + gp*Dx);
                const float4* A1 = (const float4*)(sX + (gp+16)*Dx);
                float2 bc = *(const float2*)(B1 + 2*cp);
                float r00 = bc.x, r01 = bc.y, r10 = bc.x, r11 = bc.y;
                #pragma unroll 4
                for (int d4 = 0; d4 < Dx/4; d4++) {
                    float4 a0 = A0[d4], a1 = A1[d4];
                    const float* wd = sW1s + d4*256 + 2*cp;
                    float2 w0 = *(const float2*)(wd);
                    float2 w1 = *(const float2*)(wd + 64);
                    float2 w2 = *(const float2*)(wd + 128);
                    float2 w3 = *(const float2*)(wd + 192);
                    r00 += a0.x*w0.x + a0.y*w1.x + a0.z*w2.x + a0.w*w3.x;
                    r01 += a0.x*w0.y + a0.y*w1.y + a0.z*w2.y + a0.w*w3.y;
                    r10 += a1.x*w0.x + a1.y*w1.x + a1.z*w2.x + a1.w*w3.x;
                    r11 += a1.x*w0.y + a1.y*w1.y + a1.z*w2.y + a1.w*w3.y;
                }
                *(float2*)(sHid + gp*64 + 2*cp)      = make_float2(fmaxf(r00,0.f), fmaxf(r01,0.f));
                *(float2*)(sHid + (gp+16)*64 + 2*cp) = make_float2(fmaxf(r10,0.f), fmaxf(r11,0.f));
            }
            __syncthreads();
            // scalar head: warp per node, 2 rounds
            for (int nn = 0; nn < 2; nn++) {
                int nl = w*2 + nn;
                float v = sHid[nl*64 + lane] * sW2v[lane]
                        + sHid[nl*64 + 32 + lane] * sW2v[32 + lane];
                #pragma unroll
                for (int o = 16; o > 0; o >>= 1) v += __shfl_xor_sync(full, v, o);
                if (lane == 0) {
                    float sig = 1.f / (1.f + expf(-(v + B2)));
                    int node = nodeBase + nl;
                    if (m == 0) g_kap[node] = sig; else g_f[m-1][node] = sig;
                }
            }
        }
        if (bid == 0) {   // scalar m1 = sigmoid(MLP(1))
            float* s1 = sm + 15000;
            float* s2 = s1 + 64;
            __syncthreads();
            if (tid < 64) s1[tid] = fmaxf(wmW1[tid] + wmb1[tid], 0.f);
            __syncthreads();
            if (tid < 32) {
                float a = wmb2[tid];
                #pragma unroll
                for (int i = 0; i < 64; i++) a += s1[i] * wmW2[i*32 + tid];
                s2[tid] = fmaxf(a, 0.f);
            }
            __syncthreads();
            if (tid == 0) {
                float s = wmb3[0];
                #pragma unroll
                for (int i = 0; i < 32; i++) s += s2[i] * wmW3[i];
                g_m1 = 1.f / (1.f + expf(-s));
            }
        }
    }

    gridbar(0);   // kap/f/m1/adj ready

    // ================= PHASE 2: prune (blocks 0-7) + curv1 + gin0 =========
    if (bid < Bx) {   // prune batch b = bid; 1 element per thread
        int b = bid;
        float* sv = sm;         // 512
        float* so = sm + 512;   // 512
        float v = g_kap[b*Nx + tid];
        sv[tid] = v; so[tid] = v;
        __syncthreads();
        for (int k = 2; k <= Nx; k <<= 1)
            for (int j = k >> 1; j > 0; j >>= 1) {
                int ixj = tid ^ j;
                if (ixj > tid) {
                    float a = sv[tid], c = sv[ixj];
                    bool up = ((tid & k) == 0);
                    if ((a > c) == up) { sv[tid] = c; sv[ixj] = a; }
                }
                __syncthreads();
            }
        int p = *p_ptr;
        float keepA = 1.f, keepB = 1.f;
        for (int phase = 0; phase < 2; phase++) {
            int kk = (Nx * p * (phase+1)) / 100;
            bool removed = false;
            if (kk >= 1) {
                float T = sv[Nx - kk];
                int cgt = __syncthreads_count(so[tid] > T);
                int need = kk - cgt;
                removed = (so[tid] > T);
                bool eq = (so[tid] == T) && (need > 0);
                unsigned bal = __ballot_sync(full, eq);
                if (lane == 0) wcnt[w] = __popc(bal);
                __syncthreads();
                int off = 0;
                #pragma unroll
                for (int i = 0; i < 16; i++) if (i < w) off += wcnt[i];
                int rank = off + __popc(bal & ((1u << lane) - 1u));
                if (eq && rank < need) removed = true;
            }
            if (phase == 0) keepA = removed ? 0.f : 1.f;
            else           keepB = removed ? 0.f : 1.f;
            __syncthreads();
        }
        unsigned mA = __ballot_sync(full, keepA != 0.f);
        unsigned mB = __ballot_sync(full, keepA * keepB != 0.f);
        if (lane == 0) { g_kmask1[b*16 + w] = mA; g_kmask2[b*16 + w] = mB; }
        __syncthreads();
    }

    {   // curv pass 1: batch = bid>>4, 32 rows/block, 2 rows/warp
        int b2 = bid >> 4;
        int rowbase = (bid & 15) * 32;
        __syncthreads();
        for (int i = tid; i < FNx*Nx; i += NT)
            sm[i] = g_f[i >> 9][b2*Nx + (i & 511)];
        __syncthreads();
        float m1 = g_m1;
        unsigned myw[2];
        #pragma unroll
        for (int k = 0; k < 2; k++) {
            int row = rowbase + w*2 + k;
            myw[k] = (lane < 16) ? g_adj[(size_t)(b2*Nx + row)*16 + lane] : 0u;
        }
        int degi[2];
        #pragma unroll
        for (int k = 0; k < 2; k++) degi[k] = __popc(myw[k]);
        float u1[2][FNx], u2[2][FNx];
        #pragma unroll
        for (int k = 0; k < 2; k++)
            #pragma unroll
            for (int i = 0; i < FNx; i++) { u1[k][i] = 0.f; u2[k][i] = 0.f; }
        #pragma unroll
        for (int c = 0; c < 16; c++) {
            float fv[FNx];
            #pragma unroll
            for (int i = 0; i < FNx; i++) fv[i] = sm[i*512 + c*32 + lane];
            #pragma unroll
            for (int k = 0; k < 2; k++) {
                unsigned bits = __shfl_sync(full, myw[k], c);
                float sel = (float)((bits >> lane) & 1u);
                #pragma unroll
                for (int i = 0; i < FNx; i++) {
                    u1[k][i] += sel * fv[i];
                    u2[k][i] += sel * fv[i] * fv[i];
                }
            }
        }
        #pragma unroll
        for (int o = 16; o > 0; o >>= 1) {
            #pragma unroll
            for (int k = 0; k < 2; k++) {
                degi[k] += __shfl_xor_sync(full, degi[k], o);
                #pragma unroll
                for (int i = 0; i < FNx; i++) {
                    u1[k][i] += __shfl_xor_sync(full, u1[k][i], o);
                    u2[k][i] += __shfl_xor_sync(full, u2[k][i], o);
                }
            }
        }
        if (lane == 0) {
            #pragma unroll
            for (int k = 0; k < 2; k++) {
                int row = rowbase + w*2 + k;
                int idx = b2*Nx + row;
                float deg = (float)degi[k];
                g_deg[idx] = deg;
                #pragma unroll
                for (int i = 0; i < FNx; i++) {
                    float fr = sm[i*512 + row];
                    g_u1[i][idx] = u1[k][i];
                    float gam = 0.5f*m1*(fr*fr*deg - 2.f*fr*u1[k][i] + u2[k][i]);
                    float df  = m1*(fr*deg - u1[k][i]);
                    g_gamma[i][idx] = gam; g_df[i][idx] = df; g_fdf[i][idx] = fr*df;
                }
            }
        }
        __syncthreads();
    }

    {   // gin layer 0 (partials -> cols 128..191)
        float eps1 = 1.f + eps[0];
        gin_phase<128>(sm, X, nullptr, eps1, g0W1, g0b1, g0W2, g0b2, &g_h[0][0], 128);
    }

    gridbar(1);   // gamma/df/fdf, kmask1, h0 ready

    // ================= PHASE 3: curv2 + gin1 ==============================
    {   // curv pass 2
        int b2 = bid >> 4;
        int rowbase = (bid & 15) * 32;
        float* sgam = sm;            // 3*512
        float* sdf  = sm + 1536;
        float* sfd  = sm + 3072;
        for (int i = tid; i < FNx*Nx; i += NT) {
            int f = i >> 9, j = i & 511, id2 = b2*Nx + j;
            sgam[f*512 + j] = g_gamma[f][id2];
            sdf[f*512 + j]  = g_df[f][id2];
            sfd[f*512 + j]  = g_fdf[f][id2];
        }
        __syncthreads();
        float m1 = g_m1;
        unsigned myw[2];
        #pragma unroll
        for (int k = 0; k < 2; k++) {
            int row = rowbase + w*2 + k;
            myw[k] = (lane < 16) ? g_adj[(size_t)(b2*Nx + row)*16 + lane] : 0u;
        }
        float v1[2][FNx], v2[2][FNx], v3[2][FNx];
        #pragma unroll
        for (int k = 0; k < 2; k++)
            #pragma unroll
            for (int i = 0; i < FNx; i++) { v1[k][i]=0.f; v2[k][i]=0.f; v3[k][i]=0.f; }
        #pragma unroll
        for (int c = 0; c < 16; c++) {
            int j = c*32 + lane;
            float gv[FNx], dv[FNx], fv[FNx];
            #pragma unroll
            for (int i = 0; i < FNx; i++) {
                gv[i] = sgam[i*512 + j]; dv[i] = sdf[i*512 + j]; fv[i] = sfd[i*512 + j];
            }
            #pragma unroll
            for (int k = 0; k < 2; k++) {
                unsigned bits = __shfl_sync(full, myw[k], c);
                float sel = (float)((bits >> lane) & 1u);
                #pragma unroll
                for (int i = 0; i < FNx; i++) {
                    v1[k][i] += sel * gv[i];
                    v2[k][i] += sel * dv[i];
                    v3[k][i] += sel * fv[i];
                }
            }
        }
        #pragma unroll
        for (int o = 16; o > 0; o >>= 1) {
            #pragma unroll
            for (int k = 0; k < 2; k++)
                #pragma unroll
                for (int i = 0; i < FNx; i++) {
                    v1[k][i] += __shfl_xor_sync(full, v1[k][i], o);
                    v2[k][i] += __shfl_xor_sync(full, v2[k][i], o);
                    v3[k][i] += __shfl_xor_sync(full, v3[k][i], o);
                }
        }
        if (lane == 0) {
            #pragma unroll
            for (int k = 0; k < 2; k++) {
                int row = rowbase + w*2 + k;
                int idx = b2*Nx + row;
                float deg = g_deg[idx], kap = g_kap[idx];
                float term = 0.f;
                #pragma unroll
                for (int i = 0; i < FNx; i++) {
                    float gam = sgam[i*512 + row], df = sdf[i*512 + row], fdf = sfd[i*512 + row];
                    float fr = g_f[i][idx];
                    float u1v = g_u1[i][idx];
                    float dgam = m1*(gam*deg - v1[k][i]);
                    float gfd  = 0.5f*m1*(fdf*deg - fr*v2[k][i] - df*u1v + v3[k][i]);
                    float g2 = 0.5f*dgam - gfd;
                    term += fmaxf(kap*gam - g2, 0.f);
                }
                g_rowloss[idx] = term - 3.f*kap;
            }
        }
        __syncthreads();
    }
    {   // gin layer 1 (partials -> cols 192..255)
        float eps1 = 1.f + eps[1];
        gin_phase<64>(sm, &g_h[0][0], g_kmask1, eps1, g1W1, g1b1, g1W2, g1b2, &g_h[1][0], 192);
    }

    gridbar(2);   // h1, rowloss ready

    // ================= PHASE 4: gin2 (no h write) + loss reduce ===========
    {
        float eps1 = 1.f + eps[2];
        gin_phase<64>(sm, &g_h[1][0], g_kmask2, eps1, g2W1, g2b1, g2W2, g2b2, nullptr, 256);
    }
    if (bid == NB-1) {   // loss reduction (rowloss ready since gridbar(2))
        float lp = 0.f;
        #pragma unroll
        for (int i = tid; i < BN; i += NT) lp += g_rowloss[i];
        float* L = sm;
        L[tid] = lp;
        __syncthreads();
        for (int o = 256; o > 0; o >>= 1) { if (tid < o) L[tid] += L[tid + o]; __syncthreads(); }
        if (tid == 0) g_loss = L[0];
    }

    gridbar(3);   // all partials + loss ready

    // ================= PHASE 5: final output GEMM =========================
    if (bid < Bx) {
        int b = bid;
        float* S = sm;
        if (tid < 320) {
            float a = 0.f;
            #pragma unroll
            for (int p2 = 0; p2 < 16; p2++) a += g_part[(b*16 + p2)*320 + tid];
            S[tid] = a;
        }
        __syncthreads();
        if (w < OUTC) {   // warp per output column
            float acc = 0.f;
            for (int f = lane; f < 320; f += 32) acc += S[f] * outW[f*OUTC + w];
            #pragma unroll
            for (int o = 16; o > 0; o >>= 1) acc += __shfl_xor_sync(full, acc, o);
            if (lane == 0) dout[b*OUTC + w] = acc + outb[w];
        }
        if (b == 0 && tid == 320 && out_size > Bx*OUTC) dout[Bx*OUTC] = g_loss;
    }
}

// ---------------- launch ----------------
extern "C" void kernel_launch(void* const* d_in, const int* in_sizes, int n_in,
                              void* d_out, int out_size) {
    const float* X    = (const float*)d_in[0];
    const float* A    = (const float*)d_in[1];
    const int*   p    = (const int*)  d_in[2];
    const float* cW1  = (const float*)d_in[3];
    const float* cb1  = (const float*)d_in[4];
    const float* cW2  = (const float*)d_in[5];
    const float* cb2  = (const float*)d_in[6];
    const float* wmW1 = (const float*)d_in[7];
    const float* wmb1 = (const float*)d_in[8];
    const float* wmW2 = (const float*)d_in[9];
    const float* wmb2 = (const float*)d_in[10];
    const float* wmW3 = (const float*)d_in[11];
    const float* wmb3 = (const float*)d_in[12];
    const float* fW1  = (const float*)d_in[13];
    const float* fb1  = (const float*)d_in[14];
    const float* fW2  = (const float*)d_in[15];
    const float* fb2  = (const float*)d_in[16];
    const float* eps  = (const float*)d_in[17];
    const float* g0W1 = (const float*)d_in[18];
    const float* g0b1 = (const float*)d_in[19];
    const float* g0W2 = (const float*)d_in[20];
    const float* g0b2 = (const float*)d_in[21];
    const float* g1W1 = (const float*)d_in[22];
    const float* g1b1 = (const float*)d_in[23];
    const float* g1W2 = (const float*)d_in[24];
    const float* g1b2 = (const float*)d_in[25];
    const float* g2W1 = (const float*)d_in[26];
    const float* g2b1 = (const float*)d_in[27];
    const float* g2W2 = (const float*)d_in[28];
    const float* g2b2 = (const float*)d_in[29];
    const float* outW = (const float*)d_in[30];
    const float* outb = (const float*)d_in[31];
    float* dout = (float*)d_out;

    // dyn smem: max phase = gin<128>: 18448 floats ≈ 73792 B
    static const int SMEM = 73792;
    cudaFuncSetAttribute((const void*)mega_kernel,
        cudaFuncAttributeMaxDynamicSharedMemorySize, SMEM);

    mega_kernel<<<NB, NT, SMEM>>>(X, A, p,
        cW1, cb1, cW2, cb2,
        wmW1, wmb1, wmW2, wmb2, wmW3, wmb3,
        fW1, fb1, fW2, fb2, eps,
        g0W1, g0b1, g0W2, g0b2,
        g1W1, g1b1, g1W2, g1b2,
        g2W1, g2b1, g2W2, g2b2,
        outW, outb, dout, out_size);
}